// round 1
// baseline (speedup 1.0000x reference)
#include <cuda_runtime.h>
#include <math.h>

#define DIM 128
#define MAX_N 100000
#define MAX_E 3200000

// ---------------- scratch (static device globals; no allocation) ----------------
__device__ float g_Y[(size_t)MAX_N * DIM];   // 51.2 MB  linear output X@W^T+b
__device__ int   g_rowptr[MAX_N + 1];
__device__ int   g_cursor[MAX_N];
__device__ int   g_scol[MAX_E];              // 12.8 MB  row-sorted cols
__device__ float g_sval[MAX_E];              // 12.8 MB  row-sorted vals

// ---------------- 1) GEMM: Y = X @ W^T + b  (X:[N,128], W:[128,128]) ------------
// Block tile 128x128, 256 threads, 8x8 micro-tile per thread, K-chunks of 32.
__global__ __launch_bounds__(256) void gemm_kernel(
    const float* __restrict__ X, const float* __restrict__ W,
    const float* __restrict__ bias, int N)
{
    __shared__ __align__(16) float Xs[32][132];   // [k][m], pad 4 (16B-aligned rows)
    __shared__ __align__(16) float Ws[32][132];   // [k][n]

    const int tid = threadIdx.x;
    const int tx  = tid & 15;     // col group (8 cols each)
    const int ty  = tid >> 4;     // row group (8 rows each)
    const int m0  = blockIdx.x * 128;

    float acc[8][8];
#pragma unroll
    for (int i = 0; i < 8; i++)
#pragma unroll
        for (int j = 0; j < 8; j++) acc[i][j] = 0.f;

    const int kk    = tid & 31;   // k within chunk (coalesced global read)
    const int rbase = tid >> 5;   // 0..7

    for (int k0 = 0; k0 < DIM; k0 += 32) {
#pragma unroll
        for (int i = 0; i < 16; i++) {
            int m  = rbase + i * 8;
            int gm = m0 + m;
            Xs[kk][m] = (gm < N) ? X[(size_t)gm * DIM + k0 + kk] : 0.f;
            Ws[kk][m] = W[(size_t)m * DIM + k0 + kk];   // m doubles as n (0..127)
        }
        __syncthreads();
#pragma unroll
        for (int k = 0; k < 32; k++) {
            float4 xa = *(const float4*)&Xs[k][ty * 8];
            float4 xb = *(const float4*)&Xs[k][ty * 8 + 4];
            float4 wa = *(const float4*)&Ws[k][tx * 8];
            float4 wb = *(const float4*)&Ws[k][tx * 8 + 4];
            float xr[8] = {xa.x, xa.y, xa.z, xa.w, xb.x, xb.y, xb.z, xb.w};
            float wr[8] = {wa.x, wa.y, wa.z, wa.w, wb.x, wb.y, wb.z, wb.w};
#pragma unroll
            for (int i = 0; i < 8; i++)
#pragma unroll
                for (int j = 0; j < 8; j++)
                    acc[i][j] += xr[i] * wr[j];
        }
        __syncthreads();
    }

    float4 ba = *(const float4*)&bias[tx * 8];
    float4 bb = *(const float4*)&bias[tx * 8 + 4];
    float br[8] = {ba.x, ba.y, ba.z, ba.w, bb.x, bb.y, bb.z, bb.w};

#pragma unroll
    for (int i = 0; i < 8; i++) {
        int gm = m0 + ty * 8 + i;
        if (gm < N) {
            float4 o0, o1;
            o0.x = acc[i][0] + br[0]; o0.y = acc[i][1] + br[1];
            o0.z = acc[i][2] + br[2]; o0.w = acc[i][3] + br[3];
            o1.x = acc[i][4] + br[4]; o1.y = acc[i][5] + br[5];
            o1.z = acc[i][6] + br[6]; o1.w = acc[i][7] + br[7];
            float* yrow = &g_Y[(size_t)gm * DIM + tx * 8];
            *(float4*)yrow       = o0;
            *(float4*)(yrow + 4) = o1;
        }
    }
}

// ---------------- 2) CSR build: histogram -> scan -> scatter --------------------
__global__ void zero_cnt_kernel(int N) {
    int i = blockIdx.x * blockDim.x + threadIdx.x;
    if (i < N) g_cursor[i] = 0;
}

__global__ void hist_kernel(const int* __restrict__ rows, int E) {
    int e = blockIdx.x * blockDim.x + threadIdx.x;
    if (e < E) atomicAdd(&g_cursor[rows[e]], 1);
}

// Single-block exclusive scan of g_cursor[0..N) -> g_rowptr; copies into g_cursor.
__global__ __launch_bounds__(1024) void scan_kernel(int N) {
    __shared__ int s[1024];
    int t = threadIdx.x;
    int chunk = (N + 1023) / 1024;
    int lo = t * chunk;
    int hi = min(N, lo + chunk);

    int sum = 0;
    for (int i = lo; i < hi; i++) sum += g_cursor[i];
    s[t] = sum;
    __syncthreads();
#pragma unroll
    for (int off = 1; off < 1024; off <<= 1) {
        int v = (t >= off) ? s[t - off] : 0;
        __syncthreads();
        s[t] += v;
        __syncthreads();
    }
    int run = s[t] - sum;   // exclusive prefix of this chunk
    for (int i = lo; i < hi; i++) {
        int c = g_cursor[i];
        g_rowptr[i] = run;
        g_cursor[i] = run;
        run += c;
    }
    if (t == 1023) g_rowptr[N] = s[1023];   // total = E
}

__global__ void scatter_kernel(const int* __restrict__ rows,
                               const int* __restrict__ cols,
                               const float* __restrict__ vals, int E) {
    int e = blockIdx.x * blockDim.x + threadIdx.x;
    if (e < E) {
        int r   = rows[e];
        int pos = atomicAdd(&g_cursor[r], 1);
        g_scol[pos] = cols[e];
        g_sval[pos] = vals[e];
    }
}

// ---------------- 3) SpMM + ELU: one warp per output row ------------------------
__global__ __launch_bounds__(256) void spmm_elu_kernel(float* __restrict__ out, int N) {
    int warp = (blockIdx.x * blockDim.x + threadIdx.x) >> 5;
    int lane = threadIdx.x & 31;
    if (warp >= N) return;

    int start = g_rowptr[warp];
    int end   = g_rowptr[warp + 1];

    const float4* __restrict__ Y4 = (const float4*)g_Y;
    float4 acc = make_float4(0.f, 0.f, 0.f, 0.f);

    for (int i = start; i < end; i++) {
        int   c = g_scol[i];
        float v = g_sval[i];
        float4 y = Y4[(size_t)c * 32 + lane];
        acc.x += v * y.x;
        acc.y += v * y.y;
        acc.z += v * y.z;
        acc.w += v * y.w;
    }

    // ELU (alpha = 1)
    acc.x = acc.x > 0.f ? acc.x : expm1f(acc.x);
    acc.y = acc.y > 0.f ? acc.y : expm1f(acc.y);
    acc.z = acc.z > 0.f ? acc.z : expm1f(acc.z);
    acc.w = acc.w > 0.f ? acc.w : expm1f(acc.w);

    ((float4*)out)[(size_t)warp * 32 + lane] = acc;
}

// ---------------- launch ---------------------------------------------------------
extern "C" void kernel_launch(void* const* d_in, const int* in_sizes, int n_in,
                              void* d_out, int out_size) {
    const float* x    = (const float*)d_in[0];
    const float* W    = (const float*)d_in[1];
    const float* b    = (const float*)d_in[2];
    const int*   rows = (const int*)d_in[3];
    const int*   cols = (const int*)d_in[4];
    const float* vals = (const float*)d_in[5];
    float* out = (float*)d_out;

    int N = in_sizes[0] / DIM;
    int E = in_sizes[3];

    gemm_kernel<<<(N + 127) / 128, 256>>>(x, W, b, N);
    zero_cnt_kernel<<<(N + 255) / 256, 256>>>(N);
    hist_kernel<<<(E + 255) / 256, 256>>>(rows, E);
    scan_kernel<<<1, 1024>>>(N);
    scatter_kernel<<<(E + 255) / 256, 256>>>(rows, cols, vals, E);
    spmm_elu_kernel<<<((size_t)N * 32 + 255) / 256, 256>>>(out, N);
}

// round 2
// speedup vs baseline: 1.4379x; 1.4379x over previous
#include <cuda_runtime.h>
#include <math.h>

#define DIM 128
#define MAX_N 100000
#define MAX_E 3200000
#define STILE 1024
#define MAX_TILES 128   // ceil(100000/1024)=98

// ---------------- scratch (static device globals; no allocation) ----------------
__device__ float g_Y[(size_t)MAX_N * DIM];   // 51.2 MB  linear output X@W^T+b
__device__ int   g_rowptr[MAX_N + 1];
__device__ int   g_cursor[MAX_N];
__device__ int2  g_edge[MAX_E];              // 25.6 MB  row-sorted (col, val-bits)
__device__ int   g_bsum[MAX_TILES];
__device__ int   g_boff[MAX_TILES];

// ---------------- 1) GEMM: Y = X @ W^T + b  (X:[N,128], W:[128,128]) ------------
__global__ __launch_bounds__(256) void gemm_kernel(
    const float* __restrict__ X, const float* __restrict__ W,
    const float* __restrict__ bias, int N)
{
    __shared__ __align__(16) float Xs[32][132];
    __shared__ __align__(16) float Ws[32][132];

    const int tid = threadIdx.x;
    const int tx  = tid & 15;
    const int ty  = tid >> 4;
    const int m0  = blockIdx.x * 128;

    float acc[8][8];
#pragma unroll
    for (int i = 0; i < 8; i++)
#pragma unroll
        for (int j = 0; j < 8; j++) acc[i][j] = 0.f;

    const int kk    = tid & 31;
    const int rbase = tid >> 5;

    for (int k0 = 0; k0 < DIM; k0 += 32) {
#pragma unroll
        for (int i = 0; i < 16; i++) {
            int m  = rbase + i * 8;
            int gm = m0 + m;
            Xs[kk][m] = (gm < N) ? X[(size_t)gm * DIM + k0 + kk] : 0.f;
            Ws[kk][m] = W[(size_t)m * DIM + k0 + kk];
        }
        __syncthreads();
#pragma unroll
        for (int k = 0; k < 32; k++) {
            float4 xa = *(const float4*)&Xs[k][ty * 8];
            float4 xb = *(const float4*)&Xs[k][ty * 8 + 4];
            float4 wa = *(const float4*)&Ws[k][tx * 8];
            float4 wb = *(const float4*)&Ws[k][tx * 8 + 4];
            float xr[8] = {xa.x, xa.y, xa.z, xa.w, xb.x, xb.y, xb.z, xb.w};
            float wr[8] = {wa.x, wa.y, wa.z, wa.w, wb.x, wb.y, wb.z, wb.w};
#pragma unroll
            for (int i = 0; i < 8; i++)
#pragma unroll
                for (int j = 0; j < 8; j++)
                    acc[i][j] += xr[i] * wr[j];
        }
        __syncthreads();
    }

    float4 ba = *(const float4*)&bias[tx * 8];
    float4 bb = *(const float4*)&bias[tx * 8 + 4];
    float br[8] = {ba.x, ba.y, ba.z, ba.w, bb.x, bb.y, bb.z, bb.w};

#pragma unroll
    for (int i = 0; i < 8; i++) {
        int gm = m0 + ty * 8 + i;
        if (gm < N) {
            float4 o0, o1;
            o0.x = acc[i][0] + br[0]; o0.y = acc[i][1] + br[1];
            o0.z = acc[i][2] + br[2]; o0.w = acc[i][3] + br[3];
            o1.x = acc[i][4] + br[4]; o1.y = acc[i][5] + br[5];
            o1.z = acc[i][6] + br[6]; o1.w = acc[i][7] + br[7];
            float* yrow = &g_Y[(size_t)gm * DIM + tx * 8];
            *(float4*)yrow       = o0;
            *(float4*)(yrow + 4) = o1;
        }
    }
}

// ---------------- 2) CSR build -----------------------------------------------
__global__ void zero_cnt_kernel(int N) {
    int i = blockIdx.x * blockDim.x + threadIdx.x;
    if (i < N) g_cursor[i] = 0;
}

__global__ void hist_kernel(const int* __restrict__ rows, int E) {
    int e = blockIdx.x * blockDim.x + threadIdx.x;
    if (e < E) atomicAdd(&g_cursor[rows[e]], 1);
}

// 2a) per-tile reduce: g_bsum[b] = sum(counts[b*STILE .. ))
__global__ __launch_bounds__(256) void reduce_tile_kernel(int N) {
    __shared__ int s[8];
    int b = blockIdx.x, t = threadIdx.x;
    int base = b * STILE;
    int sum = 0;
#pragma unroll
    for (int i = t; i < STILE; i += 256) {
        int idx = base + i;
        sum += (idx < N) ? g_cursor[idx] : 0;
    }
#pragma unroll
    for (int off = 16; off; off >>= 1)
        sum += __shfl_down_sync(0xffffffffu, sum, off);
    if ((t & 31) == 0) s[t >> 5] = sum;
    __syncthreads();
    if (t < 8) {
        sum = s[t];
#pragma unroll
        for (int off = 4; off; off >>= 1)
            sum += __shfl_down_sync(0xffu, sum, off);
        if (t == 0) g_bsum[b] = sum;
    }
}

// 2b) single block scans the (<=128) tile sums -> exclusive offsets; writes total
__global__ __launch_bounds__(128) void scan_tops_kernel(int nb, int N) {
    __shared__ int s[128];
    int t = threadIdx.x;
    int v = (t < nb) ? g_bsum[t] : 0;
    s[t] = v;
    __syncthreads();
#pragma unroll
    for (int off = 1; off < 128; off <<= 1) {
        int u = (t >= off) ? s[t - off] : 0;
        __syncthreads();
        s[t] += u;
        __syncthreads();
    }
    if (t < nb) g_boff[t] = s[t] - v;
    if (t == nb - 1) g_rowptr[N] = s[t];
}

// 2c) per-tile exclusive scan + tile offset -> rowptr & cursor
__global__ __launch_bounds__(STILE) void scan_tile_kernel(int N) {
    __shared__ int s[STILE];
    int b = blockIdx.x, t = threadIdx.x;
    int idx = b * STILE + t;
    int v = (idx < N) ? g_cursor[idx] : 0;
    s[t] = v;
    __syncthreads();
#pragma unroll
    for (int off = 1; off < STILE; off <<= 1) {
        int u = (t >= off) ? s[t - off] : 0;
        __syncthreads();
        s[t] += u;
        __syncthreads();
    }
    if (idx < N) {
        int excl = s[t] - v + g_boff[b];
        g_rowptr[idx] = excl;
        g_cursor[idx] = excl;
    }
}

__global__ void scatter_kernel(const int* __restrict__ rows,
                               const int* __restrict__ cols,
                               const float* __restrict__ vals, int E) {
    int e = blockIdx.x * blockDim.x + threadIdx.x;
    if (e < E) {
        int r   = rows[e];
        int pos = atomicAdd(&g_cursor[r], 1);
        g_edge[pos] = make_int2(cols[e], __float_as_int(vals[e]));
    }
}

// ---------------- 3) SpMM + ELU: one warp per output row ------------------------
__global__ __launch_bounds__(256) void spmm_elu_kernel(float* __restrict__ out, int N) {
    int warp = (blockIdx.x * blockDim.x + threadIdx.x) >> 5;
    int lane = threadIdx.x & 31;
    if (warp >= N) return;

    int start = g_rowptr[warp];
    int end   = g_rowptr[warp + 1];

    const float4* __restrict__ Y4 = (const float4*)g_Y;
    float4 acc = make_float4(0.f, 0.f, 0.f, 0.f);

    int i = start;
    for (; i + 1 < end; i += 2) {
        int2 e0 = g_edge[i];
        int2 e1 = g_edge[i + 1];
        float4 y0 = Y4[(size_t)e0.x * 32 + lane];
        float4 y1 = Y4[(size_t)e1.x * 32 + lane];
        float v0 = __int_as_float(e0.y);
        float v1 = __int_as_float(e1.y);
        acc.x += v0 * y0.x + v1 * y1.x;
        acc.y += v0 * y0.y + v1 * y1.y;
        acc.z += v0 * y0.z + v1 * y1.z;
        acc.w += v0 * y0.w + v1 * y1.w;
    }
    if (i < end) {
        int2 e0 = g_edge[i];
        float4 y0 = Y4[(size_t)e0.x * 32 + lane];
        float v0 = __int_as_float(e0.y);
        acc.x += v0 * y0.x;
        acc.y += v0 * y0.y;
        acc.z += v0 * y0.z;
        acc.w += v0 * y0.w;
    }

    acc.x = acc.x > 0.f ? acc.x : expm1f(acc.x);
    acc.y = acc.y > 0.f ? acc.y : expm1f(acc.y);
    acc.z = acc.z > 0.f ? acc.z : expm1f(acc.z);
    acc.w = acc.w > 0.f ? acc.w : expm1f(acc.w);

    ((float4*)out)[(size_t)warp * 32 + lane] = acc;
}

// ---------------- launch ---------------------------------------------------------
extern "C" void kernel_launch(void* const* d_in, const int* in_sizes, int n_in,
                              void* d_out, int out_size) {
    const float* x    = (const float*)d_in[0];
    const float* W    = (const float*)d_in[1];
    const float* b    = (const float*)d_in[2];
    const int*   rows = (const int*)d_in[3];
    const int*   cols = (const int*)d_in[4];
    const float* vals = (const float*)d_in[5];
    float* out = (float*)d_out;

    int N = in_sizes[0] / DIM;
    int E = in_sizes[3];
    int nb = (N + STILE - 1) / STILE;

    gemm_kernel<<<(N + 127) / 128, 256>>>(x, W, b, N);
    zero_cnt_kernel<<<(N + 255) / 256, 256>>>(N);
    hist_kernel<<<(E + 255) / 256, 256>>>(rows, E);
    reduce_tile_kernel<<<nb, 256>>>(N);
    scan_tops_kernel<<<1, 128>>>(nb, N);
    scan_tile_kernel<<<nb, STILE>>>(N);
    scatter_kernel<<<(E + 255) / 256, 256>>>(rows, cols, vals, E);
    spmm_elu_kernel<<<((size_t)N * 32 + 255) / 256, 256>>>(out, N);
}

// round 3
// speedup vs baseline: 1.7154x; 1.1929x over previous
#include <cuda_runtime.h>
#include <cuda_fp16.h>
#include <math.h>

#define DIM 128
#define MAX_N 100000
#define MAX_E 3200000
#define STILE 1024
#define MAX_TILES 128   // ceil(100000/1024)=98

// ---------------- scratch (static device globals; no allocation) ----------------
__device__ __align__(16) __half g_Yh[(size_t)MAX_N * DIM];  // 25.6 MB fp16 Y
__device__ int   g_rowptr[MAX_N + 1];
__device__ int   g_cursor[MAX_N];
__device__ int2  g_edge[MAX_E];              // 25.6 MB  row-sorted (col, val-bits)
__device__ int   g_bsum[MAX_TILES];
__device__ int   g_boff[MAX_TILES];

// ---------------- 1) GEMM: Y = X @ W^T + b  -> fp16 store ----------------------
__global__ __launch_bounds__(256) void gemm_kernel(
    const float* __restrict__ X, const float* __restrict__ W,
    const float* __restrict__ bias, int N)
{
    __shared__ __align__(16) float Xs[32][132];
    __shared__ __align__(16) float Ws[32][132];

    const int tid = threadIdx.x;
    const int tx  = tid & 15;
    const int ty  = tid >> 4;
    const int m0  = blockIdx.x * 128;

    float acc[8][8];
#pragma unroll
    for (int i = 0; i < 8; i++)
#pragma unroll
        for (int j = 0; j < 8; j++) acc[i][j] = 0.f;

    const int kk    = tid & 31;
    const int rbase = tid >> 5;

    for (int k0 = 0; k0 < DIM; k0 += 32) {
#pragma unroll
        for (int i = 0; i < 16; i++) {
            int m  = rbase + i * 8;
            int gm = m0 + m;
            Xs[kk][m] = (gm < N) ? X[(size_t)gm * DIM + k0 + kk] : 0.f;
            Ws[kk][m] = W[(size_t)m * DIM + k0 + kk];
        }
        __syncthreads();
#pragma unroll
        for (int k = 0; k < 32; k++) {
            float4 xa = *(const float4*)&Xs[k][ty * 8];
            float4 xb = *(const float4*)&Xs[k][ty * 8 + 4];
            float4 wa = *(const float4*)&Ws[k][tx * 8];
            float4 wb = *(const float4*)&Ws[k][tx * 8 + 4];
            float xr[8] = {xa.x, xa.y, xa.z, xa.w, xb.x, xb.y, xb.z, xb.w};
            float wr[8] = {wa.x, wa.y, wa.z, wa.w, wb.x, wb.y, wb.z, wb.w};
#pragma unroll
            for (int i = 0; i < 8; i++)
#pragma unroll
                for (int j = 0; j < 8; j++)
                    acc[i][j] += xr[i] * wr[j];
        }
        __syncthreads();
    }

    float4 ba = *(const float4*)&bias[tx * 8];
    float4 bb = *(const float4*)&bias[tx * 8 + 4];
    float br[8] = {ba.x, ba.y, ba.z, ba.w, bb.x, bb.y, bb.z, bb.w};

#pragma unroll
    for (int i = 0; i < 8; i++) {
        int gm = m0 + ty * 8 + i;
        if (gm < N) {
            __half2 h[4];
            h[0] = __floats2half2_rn(acc[i][0] + br[0], acc[i][1] + br[1]);
            h[1] = __floats2half2_rn(acc[i][2] + br[2], acc[i][3] + br[3]);
            h[2] = __floats2half2_rn(acc[i][4] + br[4], acc[i][5] + br[5]);
            h[3] = __floats2half2_rn(acc[i][6] + br[6], acc[i][7] + br[7]);
            *(uint4*)&g_Yh[(size_t)gm * DIM + tx * 8] = *(uint4*)h;
        }
    }
}

// ---------------- 2) CSR build -----------------------------------------------
__global__ void zero_cnt_kernel(int N) {
    int i = blockIdx.x * blockDim.x + threadIdx.x;
    if (i < N) g_cursor[i] = 0;
}

// 4 edges per thread (vectorized int4 load)
__global__ void hist_kernel(const int* __restrict__ rows, int E) {
    int t = blockIdx.x * blockDim.x + threadIdx.x;
    int e = t * 4;
    if (e + 3 < E) {
        int4 r = *(const int4*)&rows[e];
        atomicAdd(&g_cursor[r.x], 1);
        atomicAdd(&g_cursor[r.y], 1);
        atomicAdd(&g_cursor[r.z], 1);
        atomicAdd(&g_cursor[r.w], 1);
    } else {
        for (int k = e; k < E; k++) atomicAdd(&g_cursor[rows[k]], 1);
    }
}

__global__ __launch_bounds__(256) void reduce_tile_kernel(int N) {
    __shared__ int s[8];
    int b = blockIdx.x, t = threadIdx.x;
    int base = b * STILE;
    int sum = 0;
#pragma unroll
    for (int i = t; i < STILE; i += 256) {
        int idx = base + i;
        sum += (idx < N) ? g_cursor[idx] : 0;
    }
#pragma unroll
    for (int off = 16; off; off >>= 1)
        sum += __shfl_down_sync(0xffffffffu, sum, off);
    if ((t & 31) == 0) s[t >> 5] = sum;
    __syncthreads();
    if (t < 8) {
        sum = s[t];
#pragma unroll
        for (int off = 4; off; off >>= 1)
            sum += __shfl_down_sync(0xffu, sum, off);
        if (t == 0) g_bsum[b] = sum;
    }
}

__global__ __launch_bounds__(128) void scan_tops_kernel(int nb, int N) {
    __shared__ int s[128];
    int t = threadIdx.x;
    int v = (t < nb) ? g_bsum[t] : 0;
    s[t] = v;
    __syncthreads();
#pragma unroll
    for (int off = 1; off < 128; off <<= 1) {
        int u = (t >= off) ? s[t - off] : 0;
        __syncthreads();
        s[t] += u;
        __syncthreads();
    }
    if (t < nb) g_boff[t] = s[t] - v;
    if (t == nb - 1) g_rowptr[N] = s[t];
}

__global__ __launch_bounds__(STILE) void scan_tile_kernel(int N) {
    __shared__ int s[STILE];
    int b = blockIdx.x, t = threadIdx.x;
    int idx = b * STILE + t;
    int v = (idx < N) ? g_cursor[idx] : 0;
    s[t] = v;
    __syncthreads();
#pragma unroll
    for (int off = 1; off < STILE; off <<= 1) {
        int u = (t >= off) ? s[t - off] : 0;
        __syncthreads();
        s[t] += u;
        __syncthreads();
    }
    if (idx < N) {
        int excl = s[t] - v + g_boff[b];
        g_rowptr[idx] = excl;
        g_cursor[idx] = excl;
    }
}

// 4 edges per thread
__global__ void scatter_kernel(const int* __restrict__ rows,
                               const int* __restrict__ cols,
                               const float* __restrict__ vals, int E) {
    int t = blockIdx.x * blockDim.x + threadIdx.x;
    int e = t * 4;
    if (e + 3 < E) {
        int4   r = *(const int4*)&rows[e];
        int4   c = *(const int4*)&cols[e];
        float4 v = *(const float4*)&vals[e];
        int p0 = atomicAdd(&g_cursor[r.x], 1);
        int p1 = atomicAdd(&g_cursor[r.y], 1);
        int p2 = atomicAdd(&g_cursor[r.z], 1);
        int p3 = atomicAdd(&g_cursor[r.w], 1);
        g_edge[p0] = make_int2(c.x, __float_as_int(v.x));
        g_edge[p1] = make_int2(c.y, __float_as_int(v.y));
        g_edge[p2] = make_int2(c.z, __float_as_int(v.z));
        g_edge[p3] = make_int2(c.w, __float_as_int(v.w));
    } else {
        for (int k = e; k < E; k++) {
            int pos = atomicAdd(&g_cursor[rows[k]], 1);
            g_edge[pos] = make_int2(cols[k], __float_as_int(vals[k]));
        }
    }
}

// ---------------- 3) SpMM + ELU: one warp per output row, fp16 gather ----------
__global__ __launch_bounds__(256) void spmm_elu_kernel(float* __restrict__ out, int N) {
    int warp = (blockIdx.x * blockDim.x + threadIdx.x) >> 5;
    int lane = threadIdx.x & 31;
    if (warp >= N) return;

    int start = g_rowptr[warp];
    int end   = g_rowptr[warp + 1];

    // each lane owns 4 consecutive halves: 8 bytes = uint2
    const uint2* __restrict__ Yh = (const uint2*)g_Yh;
    float4 acc = make_float4(0.f, 0.f, 0.f, 0.f);

    int i = start;
    for (; i + 1 < end; i += 2) {
        int2 e0 = g_edge[i];
        int2 e1 = g_edge[i + 1];
        uint2 r0 = Yh[(size_t)e0.x * 32 + lane];
        uint2 r1 = Yh[(size_t)e1.x * 32 + lane];
        float v0 = __int_as_float(e0.y);
        float v1 = __int_as_float(e1.y);
        float2 a0 = __half22float2(*(const __half2*)&r0.x);
        float2 b0 = __half22float2(*(const __half2*)&r0.y);
        float2 a1 = __half22float2(*(const __half2*)&r1.x);
        float2 b1 = __half22float2(*(const __half2*)&r1.y);
        acc.x += v0 * a0.x + v1 * a1.x;
        acc.y += v0 * a0.y + v1 * a1.y;
        acc.z += v0 * b0.x + v1 * b1.x;
        acc.w += v0 * b0.y + v1 * b1.y;
    }
    if (i < end) {
        int2 e0 = g_edge[i];
        uint2 r0 = Yh[(size_t)e0.x * 32 + lane];
        float v0 = __int_as_float(e0.y);
        float2 a0 = __half22float2(*(const __half2*)&r0.x);
        float2 b0 = __half22float2(*(const __half2*)&r0.y);
        acc.x += v0 * a0.x;
        acc.y += v0 * a0.y;
        acc.z += v0 * b0.x;
        acc.w += v0 * b0.y;
    }

    acc.x = acc.x > 0.f ? acc.x : expm1f(acc.x);
    acc.y = acc.y > 0.f ? acc.y : expm1f(acc.y);
    acc.z = acc.z > 0.f ? acc.z : expm1f(acc.z);
    acc.w = acc.w > 0.f ? acc.w : expm1f(acc.w);

    ((float4*)out)[(size_t)warp * 32 + lane] = acc;
}

// ---------------- launch ---------------------------------------------------------
extern "C" void kernel_launch(void* const* d_in, const int* in_sizes, int n_in,
                              void* d_out, int out_size) {
    const float* x    = (const float*)d_in[0];
    const float* W    = (const float*)d_in[1];
    const float* b    = (const float*)d_in[2];
    const int*   rows = (const int*)d_in[3];
    const int*   cols = (const int*)d_in[4];
    const float* vals = (const float*)d_in[5];
    float* out = (float*)d_out;

    int N = in_sizes[0] / DIM;
    int E = in_sizes[3];
    int nb = (N + STILE - 1) / STILE;
    int e4 = (E + 3) / 4;

    // Fork a side stream so the CSR build (L2/atomic-bound) overlaps the
    // GEMM (FMA-pipe-bound). Event fork/join keeps this graph-capturable.
    cudaStream_t s1;
    cudaStreamCreateWithFlags(&s1, cudaStreamNonBlocking);
    cudaEvent_t evFork, evJoin;
    cudaEventCreateWithFlags(&evFork, cudaEventDisableTiming);
    cudaEventCreateWithFlags(&evJoin, cudaEventDisableTiming);

    cudaEventRecord(evFork, 0);
    cudaStreamWaitEvent(s1, evFork, 0);

    // CSR build chain on side stream
    zero_cnt_kernel<<<(N + 255) / 256, 256, 0, s1>>>(N);
    hist_kernel<<<(e4 + 255) / 256, 256, 0, s1>>>(rows, E);
    reduce_tile_kernel<<<nb, 256, 0, s1>>>(N);
    scan_tops_kernel<<<1, 128, 0, s1>>>(nb, N);
    scan_tile_kernel<<<nb, STILE, 0, s1>>>(N);
    scatter_kernel<<<(e4 + 255) / 256, 256, 0, s1>>>(rows, cols, vals, E);

    // GEMM on main stream (concurrent with CSR build)
    gemm_kernel<<<(N + 127) / 128, 256>>>(x, W, b, N);

    cudaEventRecord(evJoin, s1);
    cudaStreamWaitEvent(0, evJoin, 0);

    // SpMM + ELU needs both Y and CSR
    spmm_elu_kernel<<<((size_t)N * 32 + 255) / 256, 256>>>(out, N);
}